// round 14
// baseline (speedup 1.0000x reference)
#include <cuda_runtime.h>
#include <cuda_bf16.h>
#include <cuda_fp16.h>
#include <math.h>
#include <stdint.h>

#define Bsz    2
#define Tseq   2048
#define Hdim   2560
#define NH     8
#define NKV    4
#define Dh     256
#define WINDOW 1024
#define QKVN   4096          // 2048 q | 1024 k | 1024 v
#define ROWS   (Bsz*Tseq)    // 4096
#define ATTN_N (NH*Dh)       // 2048

// ---------------- scratch (device globals) -----------------------------------
__device__ __half g_qkvh[(size_t)ROWS * QKVN];  // fp16 q|k|v (GEMM out, normed in place)
__device__ float  g_sin[(size_t)ROWS * (Dh/2)];
__device__ float  g_cos[(size_t)ROWS * (Dh/2)];
__device__ int    g_zero_int = 0;

// fragment-major fp16 planes (uint32 = half2)
__device__ uint32_t g_xf_hi[(size_t)ROWS * Hdim / 2];
__device__ uint32_t g_xf_lo[(size_t)ROWS * Hdim / 2];
__device__ uint32_t g_af_hi[(size_t)ROWS * ATTN_N / 2];   // attn out, frag-major
__device__ uint32_t g_af_lo[(size_t)ROWS * ATTN_N / 2];
__device__ uint32_t g_wqkv_hi[(size_t)4096 * 2560 / 2];   // Wq|Wk|Wv concatenated
__device__ uint32_t g_wo_hi[(size_t)2560 * 2048 / 2];

// ---------------- helpers ------------------------------------------------------
__device__ __forceinline__ uint32_t smem_u32(const void* p) {
    uint32_t a;
    asm("{ .reg .u64 t; cvta.to.shared.u64 t, %1; cvt.u32.u64 %0, t; }"
        : "=r"(a) : "l"(p));
    return a;
}
__device__ __forceinline__ uint32_t h2pack(float x, float y) {
    __half2 h = __floats2half2_rn(x, y);
    return *(uint32_t*)&h;
}
__device__ __forceinline__ void split2(float x, float y, uint32_t& hi, uint32_t& lo) {
    float xh = __half2float(__float2half_rn(x));
    float yh = __half2float(__float2half_rn(y));
    hi = h2pack(xh, yh);
    lo = h2pack(x - xh, y - yh);
}
__device__ __forceinline__ void mma_f16(float* c,
    uint32_t a0, uint32_t a1, uint32_t a2, uint32_t a3,
    uint32_t b0, uint32_t b1)
{
    asm volatile(
        "mma.sync.aligned.m16n8k16.row.col.f32.f16.f16.f32 "
        "{%0,%1,%2,%3}, {%4,%5,%6,%7}, {%8,%9}, {%0,%1,%2,%3};"
        : "+f"(c[0]), "+f"(c[1]), "+f"(c[2]), "+f"(c[3])
        : "r"(a0), "r"(a1), "r"(a2), "r"(a3), "r"(b0), "r"(b1));
}
__device__ __forceinline__ void ldsm_x4(uint32_t& r0, uint32_t& r1,
                                        uint32_t& r2, uint32_t& r3, uint32_t addr)
{
    asm volatile("ldmatrix.sync.aligned.m8n8.x4.shared.b16 {%0,%1,%2,%3}, [%4];"
        : "=r"(r0), "=r"(r1), "=r"(r2), "=r"(r3) : "r"(addr));
}
__device__ __forceinline__ void ldsm_x4t(uint32_t& r0, uint32_t& r1,
                                         uint32_t& r2, uint32_t& r3, uint32_t addr)
{
    asm volatile("ldmatrix.sync.aligned.m8n8.x4.trans.shared.b16 {%0,%1,%2,%3}, [%4];"
        : "=r"(r0), "=r"(r1), "=r"(r2), "=r"(r3) : "r"(addr));
}
#define CP_ASYNC16(dst, src) \
    asm volatile("cp.async.cg.shared.global [%0], [%1], 16;" :: "r"(dst), "l"(src))
#define CP_COMMIT()   asm volatile("cp.async.commit_group;" ::: "memory")
#define CP_WAIT1()    asm volatile("cp.async.wait_group 1;" ::: "memory")
#define CP_WAIT_ALL() asm volatile("cp.async.wait_group 0;" ::: "memory")

// ---------------- rope sin/cos tables (inlined segment argmax) --------------------
__global__ void rope_table_kernel(const int* __restrict__ seg,
                                  const int* __restrict__ cur_ind) {
    __shared__ int sfirst;
    int row = blockIdx.x;
    int k   = threadIdx.x;
    int b = row / Tseq, t = row % Tseq;
    if (k == 0) {
        // first index of row maximum for this batch
        const int* sr = seg + (size_t)b * Tseq;
        int mx = -2147483647, mi = 0;
        for (int i = 0; i < Tseq; i += 128) {   // coarse scan: rows are typically all-ones
            int v = sr[i];
            if (v > mx) { mx = v; mi = i; }
        }
        // refine within the winning 128-stretch and everything before it
        int lo = (mi >= 128) ? mi - 127 : 0;
        int best = mx, bidx = mi;
        for (int i = lo; i <= mi; i++) {
            if (sr[i] >= best && i < bidx) { /* keep earliest equal */ }
        }
        // exact scan (cheap: early exit on first occurrence of global max)
        best = -2147483647;
        for (int i = 0; i < Tseq; i++) { int v = sr[i]; if (v > best) best = v; }
        for (int i = 0; i < Tseq; i++) { if (sr[i] == best) { bidx = i; break; } }
        sfirst = bidx;
    }
    __syncthreads();
    int sv = seg[row];
    long long pos = (sv != 0) ? (long long)(t - sfirst) : (1ll << 30);
    pos += (long long)cur_ind[0];
    float posf = (float)pos;
    float freq = powf(10000.0f, -((float)(2*k)) / (float)Dh);
    float ang  = posf * freq;
    g_sin[(size_t)row*128 + k] = sinf(ang);
    g_cos[(size_t)row*128 + k] = cosf(ang);
}

// ---------------- pack A (row-major [M][K] float -> frag-major fp16 hi/lo) --------
__global__ void __launch_bounds__(256) pack_a_kernel(
    const float* __restrict__ A, int K,
    uint32_t* __restrict__ Fhi, uint32_t* __restrict__ Flo)
{
    __shared__ float tile[16][68];
    int r0 = blockIdx.x * 16, k0 = blockIdx.y * 64;
    int tid = threadIdx.x;
    {
        int row = tid >> 4, q = tid & 15;
        float4 v = *(const float4*)(A + (size_t)(r0 + row) * K + k0 + q*4);
        *(float4*)&tile[row][q*4] = v;
    }
    __syncthreads();
    int k16l = tid >> 6;
    int r6   = tid & 63;
    int rpair = (r6 >> 5) * 2;
    int lane  = r6 & 31;
    int lr = lane >> 2, lc = lane & 3;
    int cb = k16l*16 + 2*lc + (rpair ? 8 : 0);
    float v00 = tile[lr    ][cb], v01 = tile[lr    ][cb+1];
    float v10 = tile[lr + 8][cb], v11 = tile[lr + 8][cb+1];
    uint32_t h0, l0, h1, l1;
    split2(v00, v01, h0, l0);
    split2(v10, v11, h1, l1);
    int K16 = K >> 4;
    size_t off = ((size_t)blockIdx.x * K16 + blockIdx.y*4 + k16l) * 128 + lane*4 + rpair;
    Fhi[off]   = h0;  Flo[off]   = l0;
    Fhi[off+1] = h1;  Flo[off+1] = l1;
}

// ---------------- pack ALL weights (Wq|Wk|Wv|Wo) in one launch --------------------
// grid = (20, 832). nb<512: QKV space (K=2560). nb>=512: Wo (K=2048, x<16 only).
__global__ void __launch_bounds__(256) pack_wall_kernel(
    const float* __restrict__ Wq, const float* __restrict__ Wk,
    const float* __restrict__ Wv, const float* __restrict__ Wo,
    uint32_t* __restrict__ Fqkv, uint32_t* __restrict__ Fo)
{
    __shared__ float tile[128][9];
    int nb = blockIdx.y;
    const float* W; int N; int n0; int K; uint32_t* F; int nbo;
    if (nb < 512) {
        K = 2560; F = Fqkv; nbo = nb;
        if (nb < 256)      { W = Wq; N = 2048; n0 = nb * 8; }
        else if (nb < 384) { W = Wk; N = 1024; n0 = (nb - 256) * 8; }
        else               { W = Wv; N = 1024; n0 = (nb - 384) * 8; }
    } else {
        if (blockIdx.x >= 16) return;
        K = 2048; F = Fo; nbo = nb - 512;
        W = Wo; N = 2560; n0 = nbo * 8;
    }
    int k0 = blockIdx.x * 128;
    int tid = threadIdx.x;
    {
        int kl = tid >> 1, half = tid & 1;
        float4 v = *(const float4*)(W + (size_t)(k0 + kl) * N + n0 + half*4);
        tile[kl][half*4 + 0] = v.x;
        tile[kl][half*4 + 1] = v.y;
        tile[kl][half*4 + 2] = v.z;
        tile[kl][half*4 + 3] = v.w;
    }
    __syncthreads();
    int k16l = tid >> 5, lane = tid & 31;
    int lr = lane >> 2, lc = lane & 3;
    int kb = k16l * 16;
    float v0 = tile[kb + 2*lc    ][lr];
    float v1 = tile[kb + 2*lc + 1][lr];
    float v2 = tile[kb + 2*lc + 8][lr];
    float v3 = tile[kb + 2*lc + 9][lr];
    int K16 = K >> 4;
    size_t off = ((size_t)nbo * K16 + blockIdx.x*8 + k16l) * 64 + lane*2;
    F[off]   = h2pack(__half2float(__float2half_rn(v0)), __half2float(__float2half_rn(v1)));
    F[off+1] = h2pack(__half2float(__float2half_rn(v2)), __half2float(__float2half_rn(v3)));
}

// ---------------- frag-major 2-term split-fp16 GEMM -------------------------------
// CTA 128x128, 8 warps (2M x 4N), warp 64x32, K chunk = 64 (4 k16 steps).
// Stage (u32): [Ahi 4096][Alo 4096][Bhi 4096] = 48KB. 2 stages, 2 CTAs/SM.
#define STG_U32 12288
#define NSTG    2
#define GEMM_SMEM (NSTG * STG_U32 * 4)   // 98304

template<typename OutT>
__global__ void __launch_bounds__(256, 2) gemm_mma_kernel(
    const uint32_t* __restrict__ Ahi, const uint32_t* __restrict__ Alo,
    const uint32_t* __restrict__ Bhi,
    OutT* __restrict__ C, int ldc, int K)
{
    extern __shared__ uint32_t smu[];
    int tid  = threadIdx.x;
    int lane = tid & 31, wid = tid >> 5;
    int wm = wid >> 2, wn = wid & 3;
    int m0 = blockIdx.y * 128, n0 = blockIdx.x * 128;
    int K16 = K >> 4;
    int rb0 = m0 >> 4, nb0 = n0 >> 3;
    const int nc = K >> 6;

    float acc[4][4][4];
#pragma unroll
    for (int i = 0; i < 4; i++)
#pragma unroll
        for (int j = 0; j < 4; j++)
#pragma unroll
            for (int r = 0; r < 4; r++) acc[i][j][r] = 0.f;

    uint32_t sbase = smem_u32(smu);

    auto issue = [&](int c, int s) {
        uint32_t sd = sbase + s * (STG_U32 * 4);
        int c4 = c * 4;
#pragma unroll
        for (int i = 0; i < 12; i++) {
            int idx = tid + i * 256;          // 16B units, 0..3071
            const uint32_t* src;
            if (idx < 2048) {
                int plane = idx >> 10, sub = idx & 1023;
                int rb = sub >> 7, k16 = (sub >> 5) & 3, j = sub & 31;
                const uint32_t* pl = plane ? Alo : Ahi;
                src = pl + ((size_t)(rb0 + rb) * K16 + c4 + k16) * 128 + j*4;
            } else {
                int sub = idx - 2048;
                int nb = sub >> 6, k16 = (sub >> 4) & 3, j = sub & 15;
                src = Bhi + ((size_t)(nb0 + nb) * K16 + c4 + k16) * 64 + j*4;
            }
            CP_ASYNC16(sd + idx * 16, src);
        }
    };

    issue(0, 0); CP_COMMIT();
    if (nc > 1) issue(1, 1);
    CP_COMMIT();

    for (int c = 0; c < nc; c++) {
        CP_WAIT1();
        __syncthreads();

        const uint32_t* sA = smu + (c & 1) * STG_U32;
        const uint32_t* pA = sA + (wm * 4) * 512 + lane * 4;
        const uint32_t* pB = sA + 8192 + (wn * 4) * 256 + lane * 2;

#pragma unroll
        for (int k16 = 0; k16 < 4; k16++) {
            uint4 AH[4], AL[4];
            uint2 BH[4];
#pragma unroll
            for (int mt = 0; mt < 4; mt++) {
                AH[mt] = *(const uint4*)(pA + mt*512 + k16*128);
                AL[mt] = *(const uint4*)(pA + 4096 + mt*512 + k16*128);
            }
#pragma unroll
            for (int nt = 0; nt < 4; nt++)
                BH[nt] = *(const uint2*)(pB + nt*256 + k16*64);
#pragma unroll
            for (int mt = 0; mt < 4; mt++)
#pragma unroll
                for (int nt = 0; nt < 4; nt++) {
                    float* cc = acc[mt][nt];
                    mma_f16(cc, AH[mt].x, AH[mt].y, AH[mt].z, AH[mt].w,
                            BH[nt].x, BH[nt].y);
                    mma_f16(cc, AL[mt].x, AL[mt].y, AL[mt].z, AL[mt].w,
                            BH[nt].x, BH[nt].y);
                }
        }

        // all warps must finish reading stage (c&1) before it is refilled
        __syncthreads();
        if (c + 2 < nc) issue(c + 2, c & 1);
        CP_COMMIT();
    }

#pragma unroll
    for (int mt = 0; mt < 4; mt++) {
        int row0 = m0 + wm*64 + mt*16 + (lane >> 2);
#pragma unroll
        for (int nt = 0; nt < 4; nt++) {
            int col = n0 + wn*32 + nt*8 + 2*(lane & 3);
            float* cc = acc[mt][nt];
            if (sizeof(OutT) == 2) {
                *(uint32_t*)((__half*)C + (size_t)row0 * ldc + col)       = h2pack(cc[0], cc[1]);
                *(uint32_t*)((__half*)C + (size_t)(row0 + 8) * ldc + col) = h2pack(cc[2], cc[3]);
            } else {
                *(float2*)((float*)C + (size_t)row0 * ldc + col)       = make_float2(cc[0], cc[1]);
                *(float2*)((float*)C + (size_t)(row0 + 8) * ldc + col) = make_float2(cc[2], cc[3]);
            }
        }
    }
}

// ---------------- RMSNorm + RoPE: one warp per (row, head) ------------------------
__global__ void __launch_bounds__(256) rmsnorm_rope_kernel(
    const float* __restrict__ qsc, const float* __restrict__ ksc)
{
    int widx = blockIdx.x * 8 + (threadIdx.x >> 5);
    int lane = threadIdx.x & 31;
    int row = widx / 12;
    int hi  = widx % 12;
    int off; const float* sc;
    if (hi < NH) { off = hi * Dh;              sc = qsc; }
    else         { off = NH*Dh + (hi-NH) * Dh; sc = ksc; }
    __half* p = g_qkvh + (size_t)row * QKVN + off;

    int c0 = lane * 4;
    __half2 a01 = *(const __half2*)(p + c0);
    __half2 a23 = *(const __half2*)(p + c0 + 2);
    __half2 b01 = *(const __half2*)(p + 128 + c0);
    __half2 b23 = *(const __half2*)(p + 128 + c0 + 2);
    float y1[4], y2[4];
    y1[0] = __half2float(__low2half(a01));  y1[1] = __half2float(__high2half(a01));
    y1[2] = __half2float(__low2half(a23));  y1[3] = __half2float(__high2half(a23));
    y2[0] = __half2float(__low2half(b01));  y2[1] = __half2float(__high2half(b01));
    y2[2] = __half2float(__low2half(b23));  y2[3] = __half2float(__high2half(b23));

    float ss = 0.f;
#pragma unroll
    for (int i = 0; i < 4; i++) ss += y1[i]*y1[i] + y2[i]*y2[i];
#pragma unroll
    for (int o = 16; o; o >>= 1) ss += __shfl_xor_sync(0xffffffffu, ss, o);
    float rms = rsqrtf(ss * (1.0f / Dh) + 1e-6f);

    float4 sc1 = *(const float4*)(sc + c0);
    float4 sc2 = *(const float4*)(sc + 128 + c0);
    float4 sn  = *(const float4*)(g_sin + (size_t)row*128 + c0);
    float4 cs  = *(const float4*)(g_cos + (size_t)row*128 + c0);
    float s1[4] = {sc1.x, sc1.y, sc1.z, sc1.w};
    float s2[4] = {sc2.x, sc2.y, sc2.z, sc2.w};
    float sn_[4] = {sn.x, sn.y, sn.z, sn.w};
    float cs_[4] = {cs.x, cs.y, cs.z, cs.w};

    float o1[4], o2[4];
#pragma unroll
    for (int i = 0; i < 4; i++) {
        float u = y1[i] * rms * (1.0f + s1[i]);
        float v = y2[i] * rms * (1.0f + s2[i]);
        o1[i] = u * cs_[i] - v * sn_[i];
        o2[i] = v * cs_[i] + u * sn_[i];
    }
    *(uint32_t*)(p + c0)           = h2pack(o1[0], o1[1]);
    *(uint32_t*)(p + c0 + 2)       = h2pack(o1[2], o1[3]);
    *(uint32_t*)(p + 128 + c0)     = h2pack(o2[0], o2[1]);
    *(uint32_t*)(p + 128 + c0 + 2) = h2pack(o2[2], o2[3]);
}

// ---------------- fp16 tensor-core flash attention --------------------------------
#define ABK       32
#define QS_H      264
#define KS_H      264
#define VS_H      264
#define PS_H      40
#define QS_B      0
#define KS_B      (64*QS_H*2)
#define KS_STG_B  (32*KS_H*2)
#define VS_B      (KS_B + 2*KS_STG_B)
#define VS_STG_B  16896
#define PS_B      (VS_B + 2*VS_STG_B)
#define RED_B     (PS_B + 64*PS_H*2)
#define SUM_B     (RED_B + 512)
#define ATTN_SMEM (SUM_B + 512)
#define SM_SCALE  0.0625f

__global__ void __launch_bounds__(256, 2) attn_mma_kernel(
    uint32_t* __restrict__ AFhi, uint32_t* __restrict__ AFlo)
{
    extern __shared__ char smc[];
    __half* smh = (__half*)smc;
    uint32_t sb = smem_u32(smc);
    int tid  = threadIdx.x;
    int lane = tid & 31, wid = tid >> 5;
    int lr = lane >> 2, lc = lane & 3;
    int wm = wid >> 1, wn = wid & 1;

    // longest-work-first
    int q0 = (int)(gridDim.x - 1 - blockIdx.x) * 64;
    int h  = blockIdx.y, b = blockIdx.z;
    int kvh = h >> 1;
    const __half* baseq = g_qkvh + (size_t)b * Tseq * QKVN + h * Dh;
    const __half* basek = g_qkvh + (size_t)b * Tseq * QKVN + NH*Dh + kvh * Dh;
    const __half* basev = g_qkvh + (size_t)b * Tseq * QKVN + NH*Dh + NKV*Dh + kvh * Dh;

    auto issueQ = [&]() {
#pragma unroll
        for (int i = 0; i < 8; i++) {
            int idx = tid + i * 256;
            int r = idx >> 5, c8 = idx & 31;
            CP_ASYNC16(sb + QS_B + (r*QS_H + c8*8)*2,
                       baseq + (size_t)(q0 + r) * QKVN + c8*8);
        }
    };
    auto issueKV = [&](int kt, int s) {
#pragma unroll
        for (int i = 0; i < 4; i++) {
            int idx = tid + i * 256;
            int r = idx >> 5, c8 = idx & 31;
            CP_ASYNC16(sb + KS_B + s*KS_STG_B + (r*KS_H + c8*8)*2,
                       basek + (size_t)(kt + r) * QKVN + c8*8);
        }
#pragma unroll
        for (int i = 0; i < 4; i++) {
            int idx = tid + i * 256;
            int r = idx >> 5, c8 = idx & 31;
            CP_ASYNC16(sb + VS_B + s*VS_STG_B + (r*VS_H + c8*8)*2,
                       basev + (size_t)(kt + r) * QKVN + c8*8);
        }
    };

    int kstart = q0 - (WINDOW - 1); if (kstart < 0) kstart = 0;
    int kt0 = kstart & ~(ABK - 1);
    int nt  = (q0 + 64 - kt0) >> 5;

    issueQ();
    issueKV(kt0, 0);
    CP_COMMIT();

    int arow = 16*wm + (lane & 15);
    int acol8 = (lane >> 4) * 8;
    uint32_t qs_addr = sb + QS_B + (arow*QS_H + acol8)*2;
    uint32_t ps_addr = sb + PS_B + (arow*PS_H + acol8)*2;
    int vkey = (lane & 7) + 8*((lane >> 3) & 1);
    int vd8  = 8*(lane >> 4);

    int lrow0 = 16*wm + lr;
    int qg0 = q0 + lrow0;

    float m0v = -1e30f, m1v = -1e30f, l0v = 0.f, l1v = 0.f;
    float O[16][4];
#pragma unroll
    for (int i = 0; i < 16; i++)
#pragma unroll
        for (int j = 0; j < 4; j++) O[i][j] = 0.f;

    float* Red = (float*)(smc + RED_B);
    float* Sum = (float*)(smc + SUM_B);

    for (int t = 0; t < nt; t++) {
        int kt = kt0 + t * ABK;
        int s  = t & 1;
        CP_WAIT_ALL();
        __syncthreads();
        if (t + 1 < nt) { issueKV(kt0 + (t+1)*ABK, s ^ 1); CP_COMMIT(); }

        float sacc[2][4];
#pragma unroll
        for (int nb = 0; nb < 2; nb++)
#pragma unroll
            for (int j = 0; j < 4; j++) sacc[nb][j] = 0.f;

        const __half* kb0 = smh + KS_B/2 + s*(KS_STG_B/2) + (16*wn + lr)*KS_H + 2*lc;
#pragma unroll
        for (int k16 = 0; k16 < 16; k16++) {
            uint32_t a0, a1, a2, a3;
            ldsm_x4(a0, a1, a2, a3, qs_addr + k16*32);
#pragma unroll
            for (int nb = 0; nb < 2; nb++) {
                const __half* kb = kb0 + nb*8*KS_H + k16*16;
                uint32_t b0 = *(const uint32_t*)kb;
                uint32_t b1 = *(const uint32_t*)(kb + 8);
                mma_f16(sacc[nb], a0, a1, a2, a3, b0, b1);
            }
        }

        float sv[2][4];
        float mx0 = -1e30f, mx1 = -1e30f;
#pragma unroll
        for (int nb = 0; nb < 2; nb++) {
#pragma unroll
            for (int j = 0; j < 4; j++) {
                int kg = kt + 16*wn + nb*8 + 2*lc + (j & 1);
                int qg = (j < 2) ? qg0 : (qg0 + 8);
                float v = sacc[nb][j] * SM_SCALE;
                bool valid = (kg <= qg) && (qg - kg < WINDOW);
                v = valid ? v : -1e30f;
                sv[nb][j] = v;
                if (j < 2) mx0 = fmaxf(mx0, v); else mx1 = fmaxf(mx1, v);
            }
        }
        mx0 = fmaxf(mx0, __shfl_xor_sync(0xffffffffu, mx0, 1));
        mx0 = fmaxf(mx0, __shfl_xor_sync(0xffffffffu, mx0, 2));
        mx1 = fmaxf(mx1, __shfl_xor_sync(0xffffffffu, mx1, 1));
        mx1 = fmaxf(mx1, __shfl_xor_sync(0xffffffffu, mx1, 2));
        if (lc == 0) {
            Red[wn*64 + lrow0]     = mx0;
            Red[wn*64 + lrow0 + 8] = mx1;
        }
        __syncthreads();
        float mt0 = fmaxf(Red[lrow0],     Red[64 + lrow0]);
        float mt1 = fmaxf(Red[lrow0 + 8], Red[64 + lrow0 + 8]);
        float mn0 = fmaxf(m0v, mt0);
        float mn1 = fmaxf(m1v, mt1);
        float al0 = __expf(m0v - mn0);
        float al1 = __expf(m1v - mn1);

        float s0 = 0.f, s1 = 0.f;
        float pv[2][4];
#pragma unroll
        for (int nb = 0; nb < 2; nb++) {
#pragma unroll
            for (int j = 0; j < 4; j++) {
                float mn = (j < 2) ? mn0 : mn1;
                float p = (sv[nb][j] > -1e29f) ? __expf(sv[nb][j] - mn) : 0.f;
                pv[nb][j] = p;
                if (j < 2) s0 += p; else s1 += p;
            }
        }
        s0 += __shfl_xor_sync(0xffffffffu, s0, 1);
        s0 += __shfl_xor_sync(0xffffffffu, s0, 2);
        s1 += __shfl_xor_sync(0xffffffffu, s1, 1);
        s1 += __shfl_xor_sync(0xffffffffu, s1, 2);
        if (lc == 0) {
            Sum[wn*64 + lrow0]     = s0;
            Sum[wn*64 + lrow0 + 8] = s1;
        }
#pragma unroll
        for (int nb = 0; nb < 2; nb++) {
            int col = 16*wn + nb*8 + 2*lc;
            *(uint32_t*)(smh + PS_B/2 + lrow0*PS_H + col)       = h2pack(pv[nb][0], pv[nb][1]);
            *(uint32_t*)(smh + PS_B/2 + (lrow0 + 8)*PS_H + col) = h2pack(pv[nb][2], pv[nb][3]);
        }
        __syncthreads();
        l0v = l0v * al0 + Sum[lrow0]     + Sum[64 + lrow0];
        l1v = l1v * al1 + Sum[lrow0 + 8] + Sum[64 + lrow0 + 8];
        m0v = mn0; m1v = mn1;
#pragma unroll
        for (int i = 0; i < 16; i++) {
            O[i][0] *= al0; O[i][1] *= al0;
            O[i][2] *= al1; O[i][3] *= al1;
        }

        uint32_t vs_base = sb + VS_B + s*VS_STG_B + (vkey*VS_H + 128*wn + vd8)*2;
#pragma unroll
        for (int k16 = 0; k16 < 2; k16++) {
            uint32_t p0, p1, p2, p3;
            ldsm_x4(p0, p1, p2, p3, ps_addr + k16*32);
            uint32_t va = vs_base + k16*16*VS_H*2;
#pragma unroll
            for (int nb2 = 0; nb2 < 8; nb2++) {
                uint32_t r0, r1, r2, r3;
                ldsm_x4t(r0, r1, r2, r3, va + nb2*32);
                mma_f16(O[nb2*2],     p0, p1, p2, p3, r0, r1);
                mma_f16(O[nb2*2 + 1], p0, p1, p2, p3, r2, r3);
            }
        }
    }

    float inv0 = 1.f / l0v, inv1 = 1.f / l1v;
    int rb = ((b * Tseq + q0) >> 4) + wm;
#pragma unroll
    for (int nb = 0; nb < 16; nb++) {
        int k16 = h*16 + 8*wn + (nb >> 1);
        int reg = (nb & 1) * 2;
        size_t off = ((size_t)rb * 128 + k16) * 128 + lane*4 + reg;
        uint32_t h0, l0, h1, l1;
        split2(O[nb][0]*inv0, O[nb][1]*inv0, h0, l0);
        split2(O[nb][2]*inv1, O[nb][3]*inv1, h1, l1);
        AFhi[off]   = h0;  AFlo[off]   = l0;
        AFhi[off+1] = h1;  AFlo[off+1] = l1;
    }
}

// ---------------- launch ------------------------------------------------------------
extern "C" void kernel_launch(void* const* d_in, const int* in_sizes, int n_in,
                              void* d_out, int out_size) {
    const float* x   = (const float*)d_in[0];
    const float* Wq  = (const float*)d_in[1];
    const float* Wk  = (const float*)d_in[2];
    const float* Wv  = (const float*)d_in[3];
    const float* Wo  = (const float*)d_in[4];
    const float* qsc = (const float*)d_in[5];
    const float* ksc = (const float*)d_in[6];
    const int*   seg = (const int*)d_in[7];
    float* out = (float*)d_out;

    const int* cur;
    if (n_in > 9) cur = (const int*)d_in[9];
    else {
        void* zp; cudaGetSymbolAddress(&zp, g_zero_int);
        cur = (const int*)zp;
    }

    __half* qkvh;
    cudaGetSymbolAddress((void**)&qkvh, g_qkvh);
    uint32_t *xfh, *xfl, *afh, *afl;
    cudaGetSymbolAddress((void**)&xfh, g_xf_hi); cudaGetSymbolAddress((void**)&xfl, g_xf_lo);
    cudaGetSymbolAddress((void**)&afh, g_af_hi); cudaGetSymbolAddress((void**)&afl, g_af_lo);
    uint32_t *wh, *woh;
    cudaGetSymbolAddress((void**)&wh,  g_wqkv_hi);
    cudaGetSymbolAddress((void**)&woh, g_wo_hi);

    cudaFuncSetAttribute(gemm_mma_kernel<__half>, cudaFuncAttributeMaxDynamicSharedMemorySize, GEMM_SMEM);
    cudaFuncSetAttribute(gemm_mma_kernel<float>,  cudaFuncAttributeMaxDynamicSharedMemorySize, GEMM_SMEM);
    cudaFuncSetAttribute(attn_mma_kernel, cudaFuncAttributeMaxDynamicSharedMemorySize, ATTN_SMEM);

    rope_table_kernel<<<ROWS, 128>>>(seg, cur);

    pack_a_kernel<<<dim3(ROWS/16, Hdim/64), 256>>>(x, Hdim, xfh, xfl);
    pack_wall_kernel<<<dim3(2560/128, 832), 256>>>(Wq, Wk, Wv, Wo, wh, woh);

    // fused QKV projection (2-term fp16 split), fp16 output
    gemm_mma_kernel<__half><<<dim3(QKVN/128, ROWS/128), 256, GEMM_SMEM>>>(
        xfh, xfl, wh, qkvh, QKVN, Hdim);

    rmsnorm_rope_kernel<<<ROWS * 12 / 8, 256>>>(qsc, ksc);

    attn_mma_kernel<<<dim3(Tseq/64, NH, Bsz), 256, ATTN_SMEM>>>(afh, afl);

    // output projection (2-term fp16 split), fp32 output
    gemm_mma_kernel<float><<<dim3(Hdim/128, ROWS/128), 256, GEMM_SMEM>>>(
        afh, afl, woh, out, Hdim, ATTN_N);
}

// round 15
// speedup vs baseline: 1.0498x; 1.0498x over previous
#include <cuda_runtime.h>
#include <cuda_bf16.h>
#include <cuda_fp16.h>
#include <math.h>
#include <stdint.h>

#define Bsz    2
#define Tseq   2048
#define Hdim   2560
#define NH     8
#define NKV    4
#define Dh     256
#define WINDOW 1024
#define QKVN   4096          // 2048 q | 1024 k | 1024 v
#define ROWS   (Bsz*Tseq)    // 4096
#define ATTN_N (NH*Dh)       // 2048

// ---------------- scratch (device globals) -----------------------------------
__device__ __half g_qkvh[(size_t)ROWS * QKVN];  // fp16 q|k|v (GEMM out, normed in place)
__device__ float  g_sin[(size_t)ROWS * (Dh/2)];
__device__ float  g_cos[(size_t)ROWS * (Dh/2)];
__device__ int    g_first[Bsz];
__device__ int    g_zero_int = 0;

// fragment-major fp16 planes (uint32 = half2)
__device__ uint32_t g_xf_hi[(size_t)ROWS * Hdim / 2];
__device__ uint32_t g_xf_lo[(size_t)ROWS * Hdim / 2];
__device__ uint32_t g_af_hi[(size_t)ROWS * ATTN_N / 2];   // attn out, frag-major
__device__ uint32_t g_af_lo[(size_t)ROWS * ATTN_N / 2];
__device__ uint32_t g_wqkv_hi[(size_t)4096 * 2560 / 2];   // Wq|Wk|Wv concatenated
__device__ uint32_t g_wo_hi[(size_t)2560 * 2048 / 2];

// ---------------- helpers ------------------------------------------------------
__device__ __forceinline__ uint32_t smem_u32(const void* p) {
    uint32_t a;
    asm("{ .reg .u64 t; cvta.to.shared.u64 t, %1; cvt.u32.u64 %0, t; }"
        : "=r"(a) : "l"(p));
    return a;
}
__device__ __forceinline__ uint32_t h2pack(float x, float y) {
    __half2 h = __floats2half2_rn(x, y);
    return *(uint32_t*)&h;
}
__device__ __forceinline__ void split2(float x, float y, uint32_t& hi, uint32_t& lo) {
    float xh = __half2float(__float2half_rn(x));
    float yh = __half2float(__float2half_rn(y));
    hi = h2pack(xh, yh);
    lo = h2pack(x - xh, y - yh);
}
__device__ __forceinline__ void mma_f16(float* c,
    uint32_t a0, uint32_t a1, uint32_t a2, uint32_t a3,
    uint32_t b0, uint32_t b1)
{
    asm volatile(
        "mma.sync.aligned.m16n8k16.row.col.f32.f16.f16.f32 "
        "{%0,%1,%2,%3}, {%4,%5,%6,%7}, {%8,%9}, {%0,%1,%2,%3};"
        : "+f"(c[0]), "+f"(c[1]), "+f"(c[2]), "+f"(c[3])
        : "r"(a0), "r"(a1), "r"(a2), "r"(a3), "r"(b0), "r"(b1));
}
__device__ __forceinline__ void ldsm_x4(uint32_t& r0, uint32_t& r1,
                                        uint32_t& r2, uint32_t& r3, uint32_t addr)
{
    asm volatile("ldmatrix.sync.aligned.m8n8.x4.shared.b16 {%0,%1,%2,%3}, [%4];"
        : "=r"(r0), "=r"(r1), "=r"(r2), "=r"(r3) : "r"(addr));
}
__device__ __forceinline__ void ldsm_x4t(uint32_t& r0, uint32_t& r1,
                                         uint32_t& r2, uint32_t& r3, uint32_t addr)
{
    asm volatile("ldmatrix.sync.aligned.m8n8.x4.trans.shared.b16 {%0,%1,%2,%3}, [%4];"
        : "=r"(r0), "=r"(r1), "=r"(r2), "=r"(r3) : "r"(addr));
}
#define CP_ASYNC16(dst, src) \
    asm volatile("cp.async.cg.shared.global [%0], [%1], 16;" :: "r"(dst), "l"(src))
#define CP_COMMIT()   asm volatile("cp.async.commit_group;" ::: "memory")
#define CP_WAIT1()    asm volatile("cp.async.wait_group 1;" ::: "memory")
#define CP_WAIT_ALL() asm volatile("cp.async.wait_group 0;" ::: "memory")

// ---------------- pos helper (parallel, 2 blocks) ----------------------------------
__global__ void seg_first_kernel(const int* __restrict__ seg) {
    __shared__ int smax;
    __shared__ int sidx;
    int b = blockIdx.x, tid = threadIdx.x;
    if (tid == 0) { smax = -2147483647; sidx = 2147483647; }
    __syncthreads();
    int mx = -2147483647;
    for (int t = tid; t < Tseq; t += blockDim.x) mx = max(mx, seg[b*Tseq + t]);
    atomicMax(&smax, mx);
    __syncthreads();
    int mv = smax;
    int mi = 2147483647;
    for (int t = tid; t < Tseq; t += blockDim.x)
        if (seg[b*Tseq + t] == mv) mi = min(mi, t);
    atomicMin(&sidx, mi);
    __syncthreads();
    if (tid == 0) g_first[b] = sidx;
}

// ---------------- rope sin/cos tables --------------------------------------------
__global__ void rope_table_kernel(const int* __restrict__ seg,
                                  const int* __restrict__ cur_ind) {
    int row = blockIdx.x;
    int k   = threadIdx.x;
    int b = row / Tseq, t = row % Tseq;
    int sv = seg[row];
    long long pos = (sv != 0) ? (long long)(t - g_first[b]) : (1ll << 30);
    pos += (long long)cur_ind[0];
    float posf = (float)pos;
    float freq = powf(10000.0f, -((float)(2*k)) / (float)Dh);
    float ang  = posf * freq;
    g_sin[(size_t)row*128 + k] = sinf(ang);
    g_cos[(size_t)row*128 + k] = cosf(ang);
}

// ---------------- pack A (row-major [M][K] float -> frag-major fp16 hi/lo) --------
__global__ void __launch_bounds__(256) pack_a_kernel(
    const float* __restrict__ A, int K,
    uint32_t* __restrict__ Fhi, uint32_t* __restrict__ Flo)
{
    __shared__ float tile[16][68];
    int r0 = blockIdx.x * 16, k0 = blockIdx.y * 64;
    int tid = threadIdx.x;
    {
        int row = tid >> 4, q = tid & 15;
        float4 v = *(const float4*)(A + (size_t)(r0 + row) * K + k0 + q*4);
        *(float4*)&tile[row][q*4] = v;
    }
    __syncthreads();
    int k16l = tid >> 6;
    int r6   = tid & 63;
    int rpair = (r6 >> 5) * 2;
    int lane  = r6 & 31;
    int lr = lane >> 2, lc = lane & 3;
    int cb = k16l*16 + 2*lc + (rpair ? 8 : 0);
    float v00 = tile[lr    ][cb], v01 = tile[lr    ][cb+1];
    float v10 = tile[lr + 8][cb], v11 = tile[lr + 8][cb+1];
    uint32_t h0, l0, h1, l1;
    split2(v00, v01, h0, l0);
    split2(v10, v11, h1, l1);
    int K16 = K >> 4;
    size_t off = ((size_t)blockIdx.x * K16 + blockIdx.y*4 + k16l) * 128 + lane*4 + rpair;
    Fhi[off]   = h0;  Flo[off]   = l0;
    Fhi[off+1] = h1;  Flo[off+1] = l1;
}

// ---------------- pack ALL weights (Wq|Wk|Wv|Wo) in one launch --------------------
// grid = (20, 832). nb<512: QKV space (K=2560). nb>=512: Wo (K=2048, x<16 only).
__global__ void __launch_bounds__(256) pack_wall_kernel(
    const float* __restrict__ Wq, const float* __restrict__ Wk,
    const float* __restrict__ Wv, const float* __restrict__ Wo,
    uint32_t* __restrict__ Fqkv, uint32_t* __restrict__ Fo)
{
    __shared__ float tile[128][9];
    int nb = blockIdx.y;
    const float* W; int N; int n0; int K; uint32_t* F; int nbo;
    if (nb < 512) {
        K = 2560; F = Fqkv; nbo = nb;
        if (nb < 256)      { W = Wq; N = 2048; n0 = nb * 8; }
        else if (nb < 384) { W = Wk; N = 1024; n0 = (nb - 256) * 8; }
        else               { W = Wv; N = 1024; n0 = (nb - 384) * 8; }
    } else {
        if (blockIdx.x >= 16) return;
        K = 2048; F = Fo; nbo = nb - 512;
        W = Wo; N = 2560; n0 = nbo * 8;
    }
    int k0 = blockIdx.x * 128;
    int tid = threadIdx.x;
    {
        int kl = tid >> 1, half = tid & 1;
        float4 v = *(const float4*)(W + (size_t)(k0 + kl) * N + n0 + half*4);
        tile[kl][half*4 + 0] = v.x;
        tile[kl][half*4 + 1] = v.y;
        tile[kl][half*4 + 2] = v.z;
        tile[kl][half*4 + 3] = v.w;
    }
    __syncthreads();
    int k16l = tid >> 5, lane = tid & 31;
    int lr = lane >> 2, lc = lane & 3;
    int kb = k16l * 16;
    float v0 = tile[kb + 2*lc    ][lr];
    float v1 = tile[kb + 2*lc + 1][lr];
    float v2 = tile[kb + 2*lc + 8][lr];
    float v3 = tile[kb + 2*lc + 9][lr];
    int K16 = K >> 4;
    size_t off = ((size_t)nbo * K16 + blockIdx.x*8 + k16l) * 64 + lane*2;
    F[off]   = h2pack(__half2float(__float2half_rn(v0)), __half2float(__float2half_rn(v1)));
    F[off+1] = h2pack(__half2float(__float2half_rn(v2)), __half2float(__float2half_rn(v3)));
}

// ---------------- frag-major 2-term split-fp16 GEMM -------------------------------
// CTA 128x128, 8 warps (2M x 4N), warp 64x32, K chunk = 64 (4 k16 steps).
// Stage (u32): [Ahi 4096][Alo 4096][Bhi 4096] = 48KB. 2 stages, 2 CTAs/SM.
#define STG_U32 12288
#define NSTG    2
#define GEMM_SMEM (NSTG * STG_U32 * 4)   // 98304

template<typename OutT>
__global__ void __launch_bounds__(256, 2) gemm_mma_kernel(
    const uint32_t* __restrict__ Ahi, const uint32_t* __restrict__ Alo,
    const uint32_t* __restrict__ Bhi,
    OutT* __restrict__ C, int ldc, int K)
{
    extern __shared__ uint32_t smu[];
    int tid  = threadIdx.x;
    int lane = tid & 31, wid = tid >> 5;
    int wm = wid >> 2, wn = wid & 3;
    int m0 = blockIdx.y * 128, n0 = blockIdx.x * 128;
    int K16 = K >> 4;
    int rb0 = m0 >> 4, nb0 = n0 >> 3;
    const int nc = K >> 6;

    float acc[4][4][4];
#pragma unroll
    for (int i = 0; i < 4; i++)
#pragma unroll
        for (int j = 0; j < 4; j++)
#pragma unroll
            for (int r = 0; r < 4; r++) acc[i][j][r] = 0.f;

    uint32_t sbase = smem_u32(smu);

    auto issue = [&](int c, int s) {
        uint32_t sd = sbase + s * (STG_U32 * 4);
        int c4 = c * 4;
#pragma unroll
        for (int i = 0; i < 12; i++) {
            int idx = tid + i * 256;          // 16B units, 0..3071
            const uint32_t* src;
            if (idx < 2048) {
                int plane = idx >> 10, sub = idx & 1023;
                int rb = sub >> 7, k16 = (sub >> 5) & 3, j = sub & 31;
                const uint32_t* pl = plane ? Alo : Ahi;
                src = pl + ((size_t)(rb0 + rb) * K16 + c4 + k16) * 128 + j*4;
            } else {
                int sub = idx - 2048;
                int nb = sub >> 6, k16 = (sub >> 4) & 3, j = sub & 15;
                src = Bhi + ((size_t)(nb0 + nb) * K16 + c4 + k16) * 64 + j*4;
            }
            CP_ASYNC16(sd + idx * 16, src);
        }
    };

    issue(0, 0); CP_COMMIT();
    if (nc > 1) issue(1, 1);
    CP_COMMIT();

    for (int c = 0; c < nc; c++) {
        CP_WAIT1();
        __syncthreads();

        const uint32_t* sA = smu + (c & 1) * STG_U32;
        const uint32_t* pA = sA + (wm * 4) * 512 + lane * 4;
        const uint32_t* pB = sA + 8192 + (wn * 4) * 256 + lane * 2;

#pragma unroll
        for (int k16 = 0; k16 < 4; k16++) {
            uint4 AH[4], AL[4];
            uint2 BH[4];
#pragma unroll
            for (int mt = 0; mt < 4; mt++) {
                AH[mt] = *(const uint4*)(pA + mt*512 + k16*128);
                AL[mt] = *(const uint4*)(pA + 4096 + mt*512 + k16*128);
            }
#pragma unroll
            for (int nt = 0; nt < 4; nt++)
                BH[nt] = *(const uint2*)(pB + nt*256 + k16*64);
#pragma unroll
            for (int mt = 0; mt < 4; mt++)
#pragma unroll
                for (int nt = 0; nt < 4; nt++) {
                    float* cc = acc[mt][nt];
                    mma_f16(cc, AH[mt].x, AH[mt].y, AH[mt].z, AH[mt].w,
                            BH[nt].x, BH[nt].y);
                    mma_f16(cc, AL[mt].x, AL[mt].y, AL[mt].z, AL[mt].w,
                            BH[nt].x, BH[nt].y);
                }
        }

        // all warps must finish reading stage (c&1) before it is refilled
        __syncthreads();
        if (c + 2 < nc) issue(c + 2, c & 1);
        CP_COMMIT();
    }

#pragma unroll
    for (int mt = 0; mt < 4; mt++) {
        int row0 = m0 + wm*64 + mt*16 + (lane >> 2);
#pragma unroll
        for (int nt = 0; nt < 4; nt++) {
            int col = n0 + wn*32 + nt*8 + 2*(lane & 3);
            float* cc = acc[mt][nt];
            if (sizeof(OutT) == 2) {
                *(uint32_t*)((__half*)C + (size_t)row0 * ldc + col)       = h2pack(cc[0], cc[1]);
                *(uint32_t*)((__half*)C + (size_t)(row0 + 8) * ldc + col) = h2pack(cc[2], cc[3]);
            } else {
                *(float2*)((float*)C + (size_t)row0 * ldc + col)       = make_float2(cc[0], cc[1]);
                *(float2*)((float*)C + (size_t)(row0 + 8) * ldc + col) = make_float2(cc[2], cc[3]);
            }
        }
    }
}

// ---------------- RMSNorm + RoPE: one warp per (row, head) ------------------------
__global__ void __launch_bounds__(256) rmsnorm_rope_kernel(
    const float* __restrict__ qsc, const float* __restrict__ ksc)
{
    int widx = blockIdx.x * 8 + (threadIdx.x >> 5);
    int lane = threadIdx.x & 31;
    int row = widx / 12;
    int hi  = widx % 12;
    int off; const float* sc;
    if (hi < NH) { off = hi * Dh;              sc = qsc; }
    else         { off = NH*Dh + (hi-NH) * Dh; sc = ksc; }
    __half* p = g_qkvh + (size_t)row * QKVN + off;

    int c0 = lane * 4;
    __half2 a01 = *(const __half2*)(p + c0);
    __half2 a23 = *(const __half2*)(p + c0 + 2);
    __half2 b01 = *(const __half2*)(p + 128 + c0);
    __half2 b23 = *(const __half2*)(p + 128 + c0 + 2);
    float y1[4], y2[4];
    y1[0] = __half2float(__low2half(a01));  y1[1] = __half2float(__high2half(a01));
    y1[2] = __half2float(__low2half(a23));  y1[3] = __half2float(__high2half(a23));
    y2[0] = __half2float(__low2half(b01));  y2[1] = __half2float(__high2half(b01));
    y2[2] = __half2float(__low2half(b23));  y2[3] = __half2float(__high2half(b23));

    float ss = 0.f;
#pragma unroll
    for (int i = 0; i < 4; i++) ss += y1[i]*y1[i] + y2[i]*y2[i];
#pragma unroll
    for (int o = 16; o; o >>= 1) ss += __shfl_xor_sync(0xffffffffu, ss, o);
    float rms = rsqrtf(ss * (1.0f / Dh) + 1e-6f);

    float4 sc1 = *(const float4*)(sc + c0);
    float4 sc2 = *(const float4*)(sc + 128 + c0);
    float4 sn  = *(const float4*)(g_sin + (size_t)row*128 + c0);
    float4 cs  = *(const float4*)(g_cos + (size_t)row*128 + c0);
    float s1[4] = {sc1.x, sc1.y, sc1.z, sc1.w};
    float s2[4] = {sc2.x, sc2.y, sc2.z, sc2.w};
    float sn_[4] = {sn.x, sn.y, sn.z, sn.w};
    float cs_[4] = {cs.x, cs.y, cs.z, cs.w};

    float o1[4], o2[4];
#pragma unroll
    for (int i = 0; i < 4; i++) {
        float u = y1[i] * rms * (1.0f + s1[i]);
        float v = y2[i] * rms * (1.0f + s2[i]);
        o1[i] = u * cs_[i] - v * sn_[i];
        o2[i] = v * cs_[i] + u * sn_[i];
    }
    *(uint32_t*)(p + c0)           = h2pack(o1[0], o1[1]);
    *(uint32_t*)(p + c0 + 2)       = h2pack(o1[2], o1[3]);
    *(uint32_t*)(p + 128 + c0)     = h2pack(o2[0], o2[1]);
    *(uint32_t*)(p + 128 + c0 + 2) = h2pack(o2[2], o2[3]);
}

// ---------------- fp16 tensor-core flash attention --------------------------------
#define ABK       32
#define QS_H      264
#define KS_H      264
#define VS_H      264
#define PS_H      40
#define QS_B      0
#define KS_B      (64*QS_H*2)
#define KS_STG_B  (32*KS_H*2)
#define VS_B      (KS_B + 2*KS_STG_B)
#define VS_STG_B  16896
#define PS_B      (VS_B + 2*VS_STG_B)
#define RED_B     (PS_B + 64*PS_H*2)
#define SUM_B     (RED_B + 512)
#define ATTN_SMEM (SUM_B + 512)
#define SM_SCALE  0.0625f

__global__ void __launch_bounds__(256, 2) attn_mma_kernel(
    uint32_t* __restrict__ AFhi, uint32_t* __restrict__ AFlo)
{
    extern __shared__ char smc[];
    __half* smh = (__half*)smc;
    uint32_t sb = smem_u32(smc);
    int tid  = threadIdx.x;
    int lane = tid & 31, wid = tid >> 5;
    int lr = lane >> 2, lc = lane & 3;
    int wm = wid >> 1, wn = wid & 1;

    // longest-work-first
    int q0 = (int)(gridDim.x - 1 - blockIdx.x) * 64;
    int h  = blockIdx.y, b = blockIdx.z;
    int kvh = h >> 1;
    const __half* baseq = g_qkvh + (size_t)b * Tseq * QKVN + h * Dh;
    const __half* basek = g_qkvh + (size_t)b * Tseq * QKVN + NH*Dh + kvh * Dh;
    const __half* basev = g_qkvh + (size_t)b * Tseq * QKVN + NH*Dh + NKV*Dh + kvh * Dh;

    auto issueQ = [&]() {
#pragma unroll
        for (int i = 0; i < 8; i++) {
            int idx = tid + i * 256;
            int r = idx >> 5, c8 = idx & 31;
            CP_ASYNC16(sb + QS_B + (r*QS_H + c8*8)*2,
                       baseq + (size_t)(q0 + r) * QKVN + c8*8);
        }
    };
    auto issueKV = [&](int kt, int s) {
#pragma unroll
        for (int i = 0; i < 4; i++) {
            int idx = tid + i * 256;
            int r = idx >> 5, c8 = idx & 31;
            CP_ASYNC16(sb + KS_B + s*KS_STG_B + (r*KS_H + c8*8)*2,
                       basek + (size_t)(kt + r) * QKVN + c8*8);
        }
#pragma unroll
        for (int i = 0; i < 4; i++) {
            int idx = tid + i * 256;
            int r = idx >> 5, c8 = idx & 31;
            CP_ASYNC16(sb + VS_B + s*VS_STG_B + (r*VS_H + c8*8)*2,
                       basev + (size_t)(kt + r) * QKVN + c8*8);
        }
    };

    int kstart = q0 - (WINDOW - 1); if (kstart < 0) kstart = 0;
    int kt0 = kstart & ~(ABK - 1);
    int nt  = (q0 + 64 - kt0) >> 5;

    issueQ();
    issueKV(kt0, 0);
    CP_COMMIT();

    int arow = 16*wm + (lane & 15);
    int acol8 = (lane >> 4) * 8;
    uint32_t qs_addr = sb + QS_B + (arow*QS_H + acol8)*2;
    uint32_t ps_addr = sb + PS_B + (arow*PS_H + acol8)*2;
    int vkey = (lane & 7) + 8*((lane >> 3) & 1);
    int vd8  = 8*(lane >> 4);

    int lrow0 = 16*wm + lr;
    int qg0 = q0 + lrow0;

    float m0v = -1e30f, m1v = -1e30f, l0v = 0.f, l1v = 0.f;
    float O[16][4];
#pragma unroll
    for (int i = 0; i < 16; i++)
#pragma unroll
        for (int j = 0; j < 4; j++) O[i][j] = 0.f;

    float* Red = (float*)(smc + RED_B);
    float* Sum = (float*)(smc + SUM_B);

    for (int t = 0; t < nt; t++) {
        int kt = kt0 + t * ABK;
        int s  = t & 1;
        CP_WAIT_ALL();
        __syncthreads();
        if (t + 1 < nt) { issueKV(kt0 + (t+1)*ABK, s ^ 1); CP_COMMIT(); }

        float sacc[2][4];
#pragma unroll
        for (int nb = 0; nb < 2; nb++)
#pragma unroll
            for (int j = 0; j < 4; j++) sacc[nb][j] = 0.f;

        const __half* kb0 = smh + KS_B/2 + s*(KS_STG_B/2) + (16*wn + lr)*KS_H + 2*lc;
#pragma unroll
        for (int k16 = 0; k16 < 16; k16++) {
            uint32_t a0, a1, a2, a3;
            ldsm_x4(a0, a1, a2, a3, qs_addr + k16*32);
#pragma unroll
            for (int nb = 0; nb < 2; nb++) {
                const __half* kb = kb0 + nb*8*KS_H + k16*16;
                uint32_t b0 = *(const uint32_t*)kb;
                uint32_t b1 = *(const uint32_t*)(kb + 8);
                mma_f16(sacc[nb], a0, a1, a2, a3, b0, b1);
            }
        }

        float sv[2][4];
        float mx0 = -1e30f, mx1 = -1e30f;
#pragma unroll
        for (int nb = 0; nb < 2; nb++) {
#pragma unroll
            for (int j = 0; j < 4; j++) {
                int kg = kt + 16*wn + nb*8 + 2*lc + (j & 1);
                int qg = (j < 2) ? qg0 : (qg0 + 8);
                float v = sacc[nb][j] * SM_SCALE;
                bool valid = (kg <= qg) && (qg - kg < WINDOW);
                v = valid ? v : -1e30f;
                sv[nb][j] = v;
                if (j < 2) mx0 = fmaxf(mx0, v); else mx1 = fmaxf(mx1, v);
            }
        }
        mx0 = fmaxf(mx0, __shfl_xor_sync(0xffffffffu, mx0, 1));
        mx0 = fmaxf(mx0, __shfl_xor_sync(0xffffffffu, mx0, 2));
        mx1 = fmaxf(mx1, __shfl_xor_sync(0xffffffffu, mx1, 1));
        mx1 = fmaxf(mx1, __shfl_xor_sync(0xffffffffu, mx1, 2));
        if (lc == 0) {
            Red[wn*64 + lrow0]     = mx0;
            Red[wn*64 + lrow0 + 8] = mx1;
        }
        __syncthreads();
        float mt0 = fmaxf(Red[lrow0],     Red[64 + lrow0]);
        float mt1 = fmaxf(Red[lrow0 + 8], Red[64 + lrow0 + 8]);
        float mn0 = fmaxf(m0v, mt0);
        float mn1 = fmaxf(m1v, mt1);
        float al0 = __expf(m0v - mn0);
        float al1 = __expf(m1v - mn1);

        float s0 = 0.f, s1 = 0.f;
        float pv[2][4];
#pragma unroll
        for (int nb = 0; nb < 2; nb++) {
#pragma unroll
            for (int j = 0; j < 4; j++) {
                float mn = (j < 2) ? mn0 : mn1;
                float p = (sv[nb][j] > -1e29f) ? __expf(sv[nb][j] - mn) : 0.f;
                pv[nb][j] = p;
                if (j < 2) s0 += p; else s1 += p;
            }
        }
        s0 += __shfl_xor_sync(0xffffffffu, s0, 1);
        s0 += __shfl_xor_sync(0xffffffffu, s0, 2);
        s1 += __shfl_xor_sync(0xffffffffu, s1, 1);
        s1 += __shfl_xor_sync(0xffffffffu, s1, 2);
        if (lc == 0) {
            Sum[wn*64 + lrow0]     = s0;
            Sum[wn*64 + lrow0 + 8] = s1;
        }
#pragma unroll
        for (int nb = 0; nb < 2; nb++) {
            int col = 16*wn + nb*8 + 2*lc;
            *(uint32_t*)(smh + PS_B/2 + lrow0*PS_H + col)       = h2pack(pv[nb][0], pv[nb][1]);
            *(uint32_t*)(smh + PS_B/2 + (lrow0 + 8)*PS_H + col) = h2pack(pv[nb][2], pv[nb][3]);
        }
        __syncthreads();
        l0v = l0v * al0 + Sum[lrow0]     + Sum[64 + lrow0];
        l1v = l1v * al1 + Sum[lrow0 + 8] + Sum[64 + lrow0 + 8];
        m0v = mn0; m1v = mn1;
#pragma unroll
        for (int i = 0; i < 16; i++) {
            O[i][0] *= al0; O[i][1] *= al0;
            O[i][2] *= al1; O[i][3] *= al1;
        }

        uint32_t vs_base = sb + VS_B + s*VS_STG_B + (vkey*VS_H + 128*wn + vd8)*2;
#pragma unroll
        for (int k16 = 0; k16 < 2; k16++) {
            uint32_t p0, p1, p2, p3;
            ldsm_x4(p0, p1, p2, p3, ps_addr + k16*32);
            uint32_t va = vs_base + k16*16*VS_H*2;
#pragma unroll
            for (int nb2 = 0; nb2 < 8; nb2++) {
                uint32_t r0, r1, r2, r3;
                ldsm_x4t(r0, r1, r2, r3, va + nb2*32);
                mma_f16(O[nb2*2],     p0, p1, p2, p3, r0, r1);
                mma_f16(O[nb2*2 + 1], p0, p1, p2, p3, r2, r3);
            }
        }
    }

    float inv0 = 1.f / l0v, inv1 = 1.f / l1v;
    int rb = ((b * Tseq + q0) >> 4) + wm;
#pragma unroll
    for (int nb = 0; nb < 16; nb++) {
        int k16 = h*16 + 8*wn + (nb >> 1);
        int reg = (nb & 1) * 2;
        size_t off = ((size_t)rb * 128 + k16) * 128 + lane*4 + reg;
        uint32_t h0, l0, h1, l1;
        split2(O[nb][0]*inv0, O[nb][1]*inv0, h0, l0);
        split2(O[nb][2]*inv1, O[nb][3]*inv1, h1, l1);
        AFhi[off]   = h0;  AFlo[off]   = l0;
        AFhi[off+1] = h1;  AFlo[off+1] = l1;
    }
}

// ---------------- launch ------------------------------------------------------------
extern "C" void kernel_launch(void* const* d_in, const int* in_sizes, int n_in,
                              void* d_out, int out_size) {
    const float* x   = (const float*)d_in[0];
    const float* Wq  = (const float*)d_in[1];
    const float* Wk  = (const float*)d_in[2];
    const float* Wv  = (const float*)d_in[3];
    const float* Wo  = (const float*)d_in[4];
    const float* qsc = (const float*)d_in[5];
    const float* ksc = (const float*)d_in[6];
    const int*   seg = (const int*)d_in[7];
    float* out = (float*)d_out;

    const int* cur;
    if (n_in > 9) cur = (const int*)d_in[9];
    else {
        void* zp; cudaGetSymbolAddress(&zp, g_zero_int);
        cur = (const int*)zp;
    }

    __half* qkvh;
    cudaGetSymbolAddress((void**)&qkvh, g_qkvh);
    uint32_t *xfh, *xfl, *afh, *afl;
    cudaGetSymbolAddress((void**)&xfh, g_xf_hi); cudaGetSymbolAddress((void**)&xfl, g_xf_lo);
    cudaGetSymbolAddress((void**)&afh, g_af_hi); cudaGetSymbolAddress((void**)&afl, g_af_lo);
    uint32_t *wh, *woh;
    cudaGetSymbolAddress((void**)&wh,  g_wqkv_hi);
    cudaGetSymbolAddress((void**)&woh, g_wo_hi);

    cudaFuncSetAttribute(gemm_mma_kernel<__half>, cudaFuncAttributeMaxDynamicSharedMemorySize, GEMM_SMEM);
    cudaFuncSetAttribute(gemm_mma_kernel<float>,  cudaFuncAttributeMaxDynamicSharedMemorySize, GEMM_SMEM);
    cudaFuncSetAttribute(attn_mma_kernel, cudaFuncAttributeMaxDynamicSharedMemorySize, ATTN_SMEM);

    seg_first_kernel<<<Bsz, 256>>>(seg);
    rope_table_kernel<<<ROWS, 128>>>(seg, cur);

    pack_a_kernel<<<dim3(ROWS/16, Hdim/64), 256>>>(x, Hdim, xfh, xfl);
    pack_wall_kernel<<<dim3(2560/128, 832), 256>>>(Wq, Wk, Wv, Wo, wh, woh);

    // fused QKV projection (2-term fp16 split), fp16 output
    gemm_mma_kernel<__half><<<dim3(QKVN/128, ROWS/128), 256, GEMM_SMEM>>>(
        xfh, xfl, wh, qkvh, QKVN, Hdim);

    rmsnorm_rope_kernel<<<ROWS * 12 / 8, 256>>>(qsc, ksc);

    attn_mma_kernel<<<dim3(Tseq/64, NH, Bsz), 256, ATTN_SMEM>>>(afh, afl);

    // output projection (2-term fp16 split), fp32 output
    gemm_mma_kernel<float><<<dim3(Hdim/128, ROWS/128), 256, GEMM_SMEM>>>(
        afh, afl, woh, out, Hdim, ATTN_N);
}

// round 16
// speedup vs baseline: 1.6285x; 1.5512x over previous
#include <cuda_runtime.h>
#include <cuda_bf16.h>
#include <cuda_fp16.h>
#include <math.h>
#include <stdint.h>

#define Bsz    2
#define Tseq   2048
#define Hdim   2560
#define NH     8
#define NKV    4
#define Dh     256
#define WINDOW 1024
#define QKVN   4096          // 2048 q | 1024 k | 1024 v
#define ROWS   (Bsz*Tseq)    // 4096
#define ATTN_N (NH*Dh)       // 2048

// ---------------- scratch (device globals) -----------------------------------
__device__ __half g_qkvh[(size_t)ROWS * QKVN];  // fp16 q|k|v (GEMM out, normed in place)
__device__ float  g_sin[(size_t)ROWS * (Dh/2)];
__device__ float  g_cos[(size_t)ROWS * (Dh/2)];
__device__ int    g_first[Bsz];
__device__ int    g_zero_int = 0;

// fragment-major fp16 planes (uint32 = half2)
__device__ uint32_t g_xf_hi[(size_t)ROWS * Hdim / 2];
__device__ uint32_t g_af_hi[(size_t)ROWS * ATTN_N / 2];   // attn out, frag-major
__device__ uint32_t g_wqkv_hi[(size_t)4096 * 2560 / 2];   // Wq|Wk|Wv concatenated
__device__ uint32_t g_wo_hi[(size_t)2560 * 2048 / 2];

// ---------------- helpers ------------------------------------------------------
__device__ __forceinline__ uint32_t smem_u32(const void* p) {
    uint32_t a;
    asm("{ .reg .u64 t; cvta.to.shared.u64 t, %1; cvt.u32.u64 %0, t; }"
        : "=r"(a) : "l"(p));
    return a;
}
__device__ __forceinline__ uint32_t h2pack(float x, float y) {
    __half2 h = __floats2half2_rn(x, y);
    return *(uint32_t*)&h;
}
__device__ __forceinline__ void mma_f16(float* c,
    uint32_t a0, uint32_t a1, uint32_t a2, uint32_t a3,
    uint32_t b0, uint32_t b1)
{
    asm volatile(
        "mma.sync.aligned.m16n8k16.row.col.f32.f16.f16.f32 "
        "{%0,%1,%2,%3}, {%4,%5,%6,%7}, {%8,%9}, {%0,%1,%2,%3};"
        : "+f"(c[0]), "+f"(c[1]), "+f"(c[2]), "+f"(c[3])
        : "r"(a0), "r"(a1), "r"(a2), "r"(a3), "r"(b0), "r"(b1));
}
__device__ __forceinline__ void ldsm_x4(uint32_t& r0, uint32_t& r1,
                                        uint32_t& r2, uint32_t& r3, uint32_t addr)
{
    asm volatile("ldmatrix.sync.aligned.m8n8.x4.shared.b16 {%0,%1,%2,%3}, [%4];"
        : "=r"(r0), "=r"(r1), "=r"(r2), "=r"(r3) : "r"(addr));
}
__device__ __forceinline__ void ldsm_x4t(uint32_t& r0, uint32_t& r1,
                                         uint32_t& r2, uint32_t& r3, uint32_t addr)
{
    asm volatile("ldmatrix.sync.aligned.m8n8.x4.trans.shared.b16 {%0,%1,%2,%3}, [%4];"
        : "=r"(r0), "=r"(r1), "=r"(r2), "=r"(r3) : "r"(addr));
}
#define CP_ASYNC16(dst, src) \
    asm volatile("cp.async.cg.shared.global [%0], [%1], 16;" :: "r"(dst), "l"(src))
#define CP_COMMIT()   asm volatile("cp.async.commit_group;" ::: "memory")
#define CP_WAIT1()    asm volatile("cp.async.wait_group 1;" ::: "memory")
#define CP_WAIT_ALL() asm volatile("cp.async.wait_group 0;" ::: "memory")

// ---------------- pos helper (parallel, 2 blocks) ----------------------------------
__global__ void seg_first_kernel(const int* __restrict__ seg) {
    __shared__ int smax;
    __shared__ int sidx;
    int b = blockIdx.x, tid = threadIdx.x;
    if (tid == 0) { smax = -2147483647; sidx = 2147483647; }
    __syncthreads();
    int mx = -2147483647;
    for (int t = tid; t < Tseq; t += blockDim.x) mx = max(mx, seg[b*Tseq + t]);
    atomicMax(&smax, mx);
    __syncthreads();
    int mv = smax;
    int mi = 2147483647;
    for (int t = tid; t < Tseq; t += blockDim.x)
        if (seg[b*Tseq + t] == mv) mi = min(mi, t);
    atomicMin(&sidx, mi);
    __syncthreads();
    if (tid == 0) g_first[b] = sidx;
}

// ---------------- rope sin/cos tables --------------------------------------------
__global__ void rope_table_kernel(const int* __restrict__ seg,
                                  const int* __restrict__ cur_ind) {
    int row = blockIdx.x;
    int k   = threadIdx.x;
    int b = row / Tseq, t = row % Tseq;
    int sv = seg[row];
    long long pos = (sv != 0) ? (long long)(t - g_first[b]) : (1ll << 30);
    pos += (long long)cur_ind[0];
    float posf = (float)pos;
    float freq = powf(10000.0f, -((float)(2*k)) / (float)Dh);
    float ang  = posf * freq;
    g_sin[(size_t)row*128 + k] = sinf(ang);
    g_cos[(size_t)row*128 + k] = cosf(ang);
}

// ---------------- pack A (row-major [M][K] float -> frag-major fp16) --------------
__global__ void __launch_bounds__(256) pack_a_kernel(
    const float* __restrict__ A, int K,
    uint32_t* __restrict__ Fhi)
{
    __shared__ float tile[16][68];
    int r0 = blockIdx.x * 16, k0 = blockIdx.y * 64;
    int tid = threadIdx.x;
    {
        int row = tid >> 4, q = tid & 15;
        float4 v = *(const float4*)(A + (size_t)(r0 + row) * K + k0 + q*4);
        *(float4*)&tile[row][q*4] = v;
    }
    __syncthreads();
    int k16l = tid >> 6;
    int r6   = tid & 63;
    int rpair = (r6 >> 5) * 2;
    int lane  = r6 & 31;
    int lr = lane >> 2, lc = lane & 3;
    int cb = k16l*16 + 2*lc + (rpair ? 8 : 0);
    float v00 = tile[lr    ][cb], v01 = tile[lr    ][cb+1];
    float v10 = tile[lr + 8][cb], v11 = tile[lr + 8][cb+1];
    int K16 = K >> 4;
    size_t off = ((size_t)blockIdx.x * K16 + blockIdx.y*4 + k16l) * 128 + lane*4 + rpair;
    Fhi[off]   = h2pack(v00, v01);
    Fhi[off+1] = h2pack(v10, v11);
}

// ---------------- pack ALL weights (Wq|Wk|Wv|Wo) in one launch --------------------
__global__ void __launch_bounds__(256) pack_wall_kernel(
    const float* __restrict__ Wq, const float* __restrict__ Wk,
    const float* __restrict__ Wv, const float* __restrict__ Wo,
    uint32_t* __restrict__ Fqkv, uint32_t* __restrict__ Fo)
{
    __shared__ float tile[128][9];
    int nb = blockIdx.y;
    const float* W; int N; int n0; int K; uint32_t* F; int nbo;
    if (nb < 512) {
        K = 2560; F = Fqkv; nbo = nb;
        if (nb < 256)      { W = Wq; N = 2048; n0 = nb * 8; }
        else if (nb < 384) { W = Wk; N = 1024; n0 = (nb - 256) * 8; }
        else               { W = Wv; N = 1024; n0 = (nb - 384) * 8; }
    } else {
        if (blockIdx.x >= 16) return;
        K = 2048; F = Fo; nbo = nb - 512;
        W = Wo; N = 2560; n0 = nbo * 8;
    }
    int k0 = blockIdx.x * 128;
    int tid = threadIdx.x;
    {
        int kl = tid >> 1, half = tid & 1;
        float4 v = *(const float4*)(W + (size_t)(k0 + kl) * N + n0 + half*4);
        tile[kl][half*4 + 0] = v.x;
        tile[kl][half*4 + 1] = v.y;
        tile[kl][half*4 + 2] = v.z;
        tile[kl][half*4 + 3] = v.w;
    }
    __syncthreads();
    int k16l = tid >> 5, lane = tid & 31;
    int lr = lane >> 2, lc = lane & 3;
    int kb = k16l * 16;
    float v0 = tile[kb + 2*lc    ][lr];
    float v1 = tile[kb + 2*lc + 1][lr];
    float v2 = tile[kb + 2*lc + 8][lr];
    float v3 = tile[kb + 2*lc + 9][lr];
    int K16 = K >> 4;
    size_t off = ((size_t)nbo * K16 + blockIdx.x*8 + k16l) * 64 + lane*2;
    F[off]   = h2pack(v0, v1);
    F[off+1] = h2pack(v2, v3);
}

// ---------------- frag-major 1-term fp16 GEMM -------------------------------------
// CTA 128x128, 8 warps (2M x 4N), warp 64x32, K chunk = 64 (4 k16 steps).
// Stage (u32): [Ahi 4096][Bhi 4096] = 32KB. 3 stages, 2 CTAs/SM, single barrier.
#define STG_U32 8192
#define NSTG    3
#define GEMM_SMEM (NSTG * STG_U32 * 4)   // 98304

template<typename OutT>
__global__ void __launch_bounds__(256, 2) gemm_mma_kernel(
    const uint32_t* __restrict__ Ahi,
    const uint32_t* __restrict__ Bhi,
    OutT* __restrict__ C, int ldc, int K)
{
    extern __shared__ uint32_t smu[];
    int tid  = threadIdx.x;
    int lane = tid & 31, wid = tid >> 5;
    int wm = wid >> 2, wn = wid & 3;
    int m0 = blockIdx.y * 128, n0 = blockIdx.x * 128;
    int K16 = K >> 4;
    int rb0 = m0 >> 4, nb0 = n0 >> 3;
    const int nc = K >> 6;

    float acc[4][4][4];
#pragma unroll
    for (int i = 0; i < 4; i++)
#pragma unroll
        for (int j = 0; j < 4; j++)
#pragma unroll
            for (int r = 0; r < 4; r++) acc[i][j][r] = 0.f;

    uint32_t sbase = smem_u32(smu);

    auto issue = [&](int c, int s) {
        uint32_t sd = sbase + s * (STG_U32 * 4);
        int c4 = c * 4;
#pragma unroll
        for (int i = 0; i < 8; i++) {
            int idx = tid + i * 256;          // 16B units, 0..2047
            const uint32_t* src;
            if (idx < 1024) {
                int rb = idx >> 7, k16 = (idx >> 5) & 3, j = idx & 31;
                src = Ahi + ((size_t)(rb0 + rb) * K16 + c4 + k16) * 128 + j*4;
            } else {
                int sub = idx - 1024;
                int nb = sub >> 6, k16 = (sub >> 4) & 3, j = sub & 15;
                src = Bhi + ((size_t)(nb0 + nb) * K16 + c4 + k16) * 64 + j*4;
            }
            CP_ASYNC16(sd + idx * 16, src);
        }
    };

    issue(0, 0); CP_COMMIT();
    if (nc > 1) issue(1, 1);
    CP_COMMIT();

    for (int c = 0; c < nc; c++) {
        CP_WAIT1();
        __syncthreads();   // chunk c visible to all; all warps done with chunk c-1
        // stage (c+2)%3 held chunk c-1 -> drained by the barrier above
        if (c + 2 < nc) { issue(c + 2, (c + 2) % NSTG); CP_COMMIT(); }

        const uint32_t* sA = smu + (c % NSTG) * STG_U32;
        const uint32_t* pA = sA + (wm * 4) * 512 + lane * 4;
        const uint32_t* pB = sA + 4096 + (wn * 4) * 256 + lane * 2;

#pragma unroll
        for (int k16 = 0; k16 < 4; k16++) {
            uint4 AH[4];
            uint2 BH[4];
#pragma unroll
            for (int mt = 0; mt < 4; mt++)
                AH[mt] = *(const uint4*)(pA + mt*512 + k16*128);
#pragma unroll
            for (int nt = 0; nt < 4; nt++)
                BH[nt] = *(const uint2*)(pB + nt*256 + k16*64);
#pragma unroll
            for (int mt = 0; mt < 4; mt++)
#pragma unroll
                for (int nt = 0; nt < 4; nt++)
                    mma_f16(acc[mt][nt], AH[mt].x, AH[mt].y, AH[mt].z, AH[mt].w,
                            BH[nt].x, BH[nt].y);
        }
    }

#pragma unroll
    for (int mt = 0; mt < 4; mt++) {
        int row0 = m0 + wm*64 + mt*16 + (lane >> 2);
#pragma unroll
        for (int nt = 0; nt < 4; nt++) {
            int col = n0 + wn*32 + nt*8 + 2*(lane & 3);
            float* cc = acc[mt][nt];
            if (sizeof(OutT) == 2) {
                *(uint32_t*)((__half*)C + (size_t)row0 * ldc + col)       = h2pack(cc[0], cc[1]);
                *(uint32_t*)((__half*)C + (size_t)(row0 + 8) * ldc + col) = h2pack(cc[2], cc[3]);
            } else {
                *(float2*)((float*)C + (size_t)row0 * ldc + col)       = make_float2(cc[0], cc[1]);
                *(float2*)((float*)C + (size_t)(row0 + 8) * ldc + col) = make_float2(cc[2], cc[3]);
            }
        }
    }
}

// ---------------- RMSNorm + RoPE: one warp per (row, head) ------------------------
__global__ void __launch_bounds__(256) rmsnorm_rope_kernel(
    const float* __restrict__ qsc, const float* __restrict__ ksc)
{
    int widx = blockIdx.x * 8 + (threadIdx.x >> 5);
    int lane = threadIdx.x & 31;
    int row = widx / 12;
    int hi  = widx % 12;
    int off; const float* sc;
    if (hi < NH) { off = hi * Dh;              sc = qsc; }
    else         { off = NH*Dh + (hi-NH) * Dh; sc = ksc; }
    __half* p = g_qkvh + (size_t)row * QKVN + off;

    int c0 = lane * 4;
    __half2 a01 = *(const __half2*)(p + c0);
    __half2 a23 = *(const __half2*)(p + c0 + 2);
    __half2 b01 = *(const __half2*)(p + 128 + c0);
    __half2 b23 = *(const __half2*)(p + 128 + c0 + 2);
    float y1[4], y2[4];
    y1[0] = __half2float(__low2half(a01));  y1[1] = __half2float(__high2half(a01));
    y1[2] = __half2float(__low2half(a23));  y1[3] = __half2float(__high2half(a23));
    y2[0] = __half2float(__low2half(b01));  y2[1] = __half2float(__high2half(b01));
    y2[2] = __half2float(__low2half(b23));  y2[3] = __half2float(__high2half(b23));

    float ss = 0.f;
#pragma unroll
    for (int i = 0; i < 4; i++) ss += y1[i]*y1[i] + y2[i]*y2[i];
#pragma unroll
    for (int o = 16; o; o >>= 1) ss += __shfl_xor_sync(0xffffffffu, ss, o);
    float rms = rsqrtf(ss * (1.0f / Dh) + 1e-6f);

    float4 sc1 = *(const float4*)(sc + c0);
    float4 sc2 = *(const float4*)(sc + 128 + c0);
    float4 sn  = *(const float4*)(g_sin + (size_t)row*128 + c0);
    float4 cs  = *(const float4*)(g_cos + (size_t)row*128 + c0);
    float s1[4] = {sc1.x, sc1.y, sc1.z, sc1.w};
    float s2[4] = {sc2.x, sc2.y, sc2.z, sc2.w};
    float sn_[4] = {sn.x, sn.y, sn.z, sn.w};
    float cs_[4] = {cs.x, cs.y, cs.z, cs.w};

    float o1[4], o2[4];
#pragma unroll
    for (int i = 0; i < 4; i++) {
        float u = y1[i] * rms * (1.0f + s1[i]);
        float v = y2[i] * rms * (1.0f + s2[i]);
        o1[i] = u * cs_[i] - v * sn_[i];
        o2[i] = v * cs_[i] + u * sn_[i];
    }
    *(uint32_t*)(p + c0)           = h2pack(o1[0], o1[1]);
    *(uint32_t*)(p + c0 + 2)       = h2pack(o1[2], o1[3]);
    *(uint32_t*)(p + 128 + c0)     = h2pack(o2[0], o2[1]);
    *(uint32_t*)(p + 128 + c0 + 2) = h2pack(o2[2], o2[3]);
}

// ---------------- fp16 tensor-core flash attention --------------------------------
#define ABK       32
#define QS_H      264
#define KS_H      264
#define VS_H      264
#define PS_H      40
#define QS_B      0
#define KS_B      (64*QS_H*2)
#define KS_STG_B  (32*KS_H*2)
#define VS_B      (KS_B + 2*KS_STG_B)
#define VS_STG_B  16896
#define PS_B      (VS_B + 2*VS_STG_B)
#define RED_B     (PS_B + 64*PS_H*2)
#define SUM_B     (RED_B + 512)
#define ATTN_SMEM (SUM_B + 512)
#define SM_SCALE  0.0625f

__global__ void __launch_bounds__(256, 2) attn_mma_kernel(
    uint32_t* __restrict__ AFhi)
{
    extern __shared__ char smc[];
    __half* smh = (__half*)smc;
    uint32_t sb = smem_u32(smc);
    int tid  = threadIdx.x;
    int lane = tid & 31, wid = tid >> 5;
    int lr = lane >> 2, lc = lane & 3;
    int wm = wid >> 1, wn = wid & 1;

    // longest-work-first
    int q0 = (int)(gridDim.x - 1 - blockIdx.x) * 64;
    int h  = blockIdx.y, b = blockIdx.z;
    int kvh = h >> 1;
    const __half* baseq = g_qkvh + (size_t)b * Tseq * QKVN + h * Dh;
    const __half* basek = g_qkvh + (size_t)b * Tseq * QKVN + NH*Dh + kvh * Dh;
    const __half* basev = g_qkvh + (size_t)b * Tseq * QKVN + NH*Dh + NKV*Dh + kvh * Dh;

    auto issueQ = [&]() {
#pragma unroll
        for (int i = 0; i < 8; i++) {
            int idx = tid + i * 256;
            int r = idx >> 5, c8 = idx & 31;
            CP_ASYNC16(sb + QS_B + (r*QS_H + c8*8)*2,
                       baseq + (size_t)(q0 + r) * QKVN + c8*8);
        }
    };
    auto issueKV = [&](int kt, int s) {
#pragma unroll
        for (int i = 0; i < 4; i++) {
            int idx = tid + i * 256;
            int r = idx >> 5, c8 = idx & 31;
            CP_ASYNC16(sb + KS_B + s*KS_STG_B + (r*KS_H + c8*8)*2,
                       basek + (size_t)(kt + r) * QKVN + c8*8);
        }
#pragma unroll
        for (int i = 0; i < 4; i++) {
            int idx = tid + i * 256;
            int r = idx >> 5, c8 = idx & 31;
            CP_ASYNC16(sb + VS_B + s*VS_STG_B + (r*VS_H + c8*8)*2,
                       basev + (size_t)(kt + r) * QKVN + c8*8);
        }
    };

    int kstart = q0 - (WINDOW - 1); if (kstart < 0) kstart = 0;
    int kt0 = kstart & ~(ABK - 1);
    int nt  = (q0 + 64 - kt0) >> 5;

    issueQ();
    issueKV(kt0, 0);
    CP_COMMIT();

    int arow = 16*wm + (lane & 15);
    int acol8 = (lane >> 4) * 8;
    uint32_t qs_addr = sb + QS_B + (arow*QS_H + acol8)*2;
    uint32_t ps_addr = sb + PS_B + (arow*PS_H + acol8)*2;
    int vkey = (lane & 7) + 8*((lane >> 3) & 1);
    int vd8  = 8*(lane >> 4);

    int lrow0 = 16*wm + lr;
    int qg0 = q0 + lrow0;

    float m0v = -1e30f, m1v = -1e30f, l0v = 0.f, l1v = 0.f;
    float O[16][4];
#pragma unroll
    for (int i = 0; i < 16; i++)
#pragma unroll
        for (int j = 0; j < 4; j++) O[i][j] = 0.f;

    float* Red = (float*)(smc + RED_B);
    float* Sum = (float*)(smc + SUM_B);

    for (int t = 0; t < nt; t++) {
        int kt = kt0 + t * ABK;
        int s  = t & 1;
        CP_WAIT_ALL();
        __syncthreads();
        if (t + 1 < nt) { issueKV(kt0 + (t+1)*ABK, s ^ 1); CP_COMMIT(); }

        float sacc[2][4];
#pragma unroll
        for (int nb = 0; nb < 2; nb++)
#pragma unroll
            for (int j = 0; j < 4; j++) sacc[nb][j] = 0.f;

        const __half* kb0 = smh + KS_B/2 + s*(KS_STG_B/2) + (16*wn + lr)*KS_H + 2*lc;
#pragma unroll
        for (int k16 = 0; k16 < 16; k16++) {
            uint32_t a0, a1, a2, a3;
            ldsm_x4(a0, a1, a2, a3, qs_addr + k16*32);
#pragma unroll
            for (int nb = 0; nb < 2; nb++) {
                const __half* kb = kb0 + nb*8*KS_H + k16*16;
                uint32_t b0 = *(const uint32_t*)kb;
                uint32_t b1 = *(const uint32_t*)(kb + 8);
                mma_f16(sacc[nb], a0, a1, a2, a3, b0, b1);
            }
        }

        float sv[2][4];
        float mx0 = -1e30f, mx1 = -1e30f;
#pragma unroll
        for (int nb = 0; nb < 2; nb++) {
#pragma unroll
            for (int j = 0; j < 4; j++) {
                int kg = kt + 16*wn + nb*8 + 2*lc + (j & 1);
                int qg = (j < 2) ? qg0 : (qg0 + 8);
                float v = sacc[nb][j] * SM_SCALE;
                bool valid = (kg <= qg) && (qg - kg < WINDOW);
                v = valid ? v : -1e30f;
                sv[nb][j] = v;
                if (j < 2) mx0 = fmaxf(mx0, v); else mx1 = fmaxf(mx1, v);
            }
        }
        mx0 = fmaxf(mx0, __shfl_xor_sync(0xffffffffu, mx0, 1));
        mx0 = fmaxf(mx0, __shfl_xor_sync(0xffffffffu, mx0, 2));
        mx1 = fmaxf(mx1, __shfl_xor_sync(0xffffffffu, mx1, 1));
        mx1 = fmaxf(mx1, __shfl_xor_sync(0xffffffffu, mx1, 2));
        if (lc == 0) {
            Red[wn*64 + lrow0]     = mx0;
            Red[wn*64 + lrow0 + 8] = mx1;
        }
        __syncthreads();
        float mt0 = fmaxf(Red[lrow0],     Red[64 + lrow0]);
        float mt1 = fmaxf(Red[lrow0 + 8], Red[64 + lrow0 + 8]);
        float mn0 = fmaxf(m0v, mt0);
        float mn1 = fmaxf(m1v, mt1);
        float al0 = __expf(m0v - mn0);
        float al1 = __expf(m1v - mn1);

        float s0 = 0.f, s1 = 0.f;
        float pv[2][4];
#pragma unroll
        for (int nb = 0; nb < 2; nb++) {
#pragma unroll
            for (int j = 0; j < 4; j++) {
                float mn = (j < 2) ? mn0 : mn1;
                float p = (sv[nb][j] > -1e29f) ? __expf(sv[nb][j] - mn) : 0.f;
                pv[nb][j] = p;
                if (j < 2) s0 += p; else s1 += p;
            }
        }
        s0 += __shfl_xor_sync(0xffffffffu, s0, 1);
        s0 += __shfl_xor_sync(0xffffffffu, s0, 2);
        s1 += __shfl_xor_sync(0xffffffffu, s1, 1);
        s1 += __shfl_xor_sync(0xffffffffu, s1, 2);
        if (lc == 0) {
            Sum[wn*64 + lrow0]     = s0;
            Sum[wn*64 + lrow0 + 8] = s1;
        }
#pragma unroll
        for (int nb = 0; nb < 2; nb++) {
            int col = 16*wn + nb*8 + 2*lc;
            *(uint32_t*)(smh + PS_B/2 + lrow0*PS_H + col)       = h2pack(pv[nb][0], pv[nb][1]);
            *(uint32_t*)(smh + PS_B/2 + (lrow0 + 8)*PS_H + col) = h2pack(pv[nb][2], pv[nb][3]);
        }
        __syncthreads();
        l0v = l0v * al0 + Sum[lrow0]     + Sum[64 + lrow0];
        l1v = l1v * al1 + Sum[lrow0 + 8] + Sum[64 + lrow0 + 8];
        m0v = mn0; m1v = mn1;
#pragma unroll
        for (int i = 0; i < 16; i++) {
            O[i][0] *= al0; O[i][1] *= al0;
            O[i][2] *= al1; O[i][3] *= al1;
        }

        uint32_t vs_base = sb + VS_B + s*VS_STG_B + (vkey*VS_H + 128*wn + vd8)*2;
#pragma unroll
        for (int k16 = 0; k16 < 2; k16++) {
            uint32_t p0, p1, p2, p3;
            ldsm_x4(p0, p1, p2, p3, ps_addr + k16*32);
            uint32_t va = vs_base + k16*16*VS_H*2;
#pragma unroll
            for (int nb2 = 0; nb2 < 8; nb2++) {
                uint32_t r0, r1, r2, r3;
                ldsm_x4t(r0, r1, r2, r3, va + nb2*32);
                mma_f16(O[nb2*2],     p0, p1, p2, p3, r0, r1);
                mma_f16(O[nb2*2 + 1], p0, p1, p2, p3, r2, r3);
            }
        }
    }

    // ---- epilogue: frag-major fp16 (A of Wo GEMM, hi plane only) ----
    float inv0 = 1.f / l0v, inv1 = 1.f / l1v;
    int rb = ((b * Tseq + q0) >> 4) + wm;
#pragma unroll
    for (int nb = 0; nb < 16; nb++) {
        int k16 = h*16 + 8*wn + (nb >> 1);
        int reg = (nb & 1) * 2;
        size_t off = ((size_t)rb * 128 + k16) * 128 + lane*4 + reg;
        AFhi[off]   = h2pack(O[nb][0]*inv0, O[nb][1]*inv0);
        AFhi[off+1] = h2pack(O[nb][2]*inv1, O[nb][3]*inv1);
    }
}

// ---------------- launch ------------------------------------------------------------
extern "C" void kernel_launch(void* const* d_in, const int* in_sizes, int n_in,
                              void* d_out, int out_size) {
    const float* x   = (const float*)d_in[0];
    const float* Wq  = (const float*)d_in[1];
    const float* Wk  = (const float*)d_in[2];
    const float* Wv  = (const float*)d_in[3];
    const float* Wo  = (const float*)d_in[4];
    const float* qsc = (const float*)d_in[5];
    const float* ksc = (const float*)d_in[6];
    const int*   seg = (const int*)d_in[7];
    float* out = (float*)d_out;

    const int* cur;
    if (n_in > 9) cur = (const int*)d_in[9];
    else {
        void* zp; cudaGetSymbolAddress(&zp, g_zero_int);
        cur = (const int*)zp;
    }

    __half* qkvh;
    cudaGetSymbolAddress((void**)&qkvh, g_qkvh);
    uint32_t *xfh, *afh;
    cudaGetSymbolAddress((void**)&xfh, g_xf_hi);
    cudaGetSymbolAddress((void**)&afh, g_af_hi);
    uint32_t *wh, *woh;
    cudaGetSymbolAddress((void**)&wh,  g_wqkv_hi);
    cudaGetSymbolAddress((void**)&woh, g_wo_hi);

    cudaFuncSetAttribute(gemm_mma_kernel<__half>, cudaFuncAttributeMaxDynamicSharedMemorySize, GEMM_SMEM);
    cudaFuncSetAttribute(gemm_mma_kernel<float>,  cudaFuncAttributeMaxDynamicSharedMemorySize, GEMM_SMEM);
    cudaFuncSetAttribute(attn_mma_kernel, cudaFuncAttributeMaxDynamicSharedMemorySize, ATTN_SMEM);

    seg_first_kernel<<<Bsz, 256>>>(seg);
    rope_table_kernel<<<ROWS, 128>>>(seg, cur);

    pack_a_kernel<<<dim3(ROWS/16, Hdim/64), 256>>>(x, Hdim, xfh);
    pack_wall_kernel<<<dim3(2560/128, 832), 256>>>(Wq, Wk, Wv, Wo, wh, woh);

    // fused QKV projection (fp16 GEMM, fp32 accum), fp16 output
    gemm_mma_kernel<__half><<<dim3(QKVN/128, ROWS/128), 256, GEMM_SMEM>>>(
        xfh, wh, qkvh, QKVN, Hdim);

    rmsnorm_rope_kernel<<<ROWS * 12 / 8, 256>>>(qsc, ksc);

    attn_mma_kernel<<<dim3(Tseq/64, NH, Bsz), 256, ATTN_SMEM>>>(afh);

    // output projection (fp16 GEMM, fp32 accum), fp32 output
    gemm_mma_kernel<float><<<dim3(Hdim/128, ROWS/128), 256, GEMM_SMEM>>>(
        afh, woh, out, Hdim, ATTN_N);
}